// round 4
// baseline (speedup 1.0000x reference)
#include <cuda_runtime.h>
#include <cstdint>

// ---------------------------------------------------------------------------
// GCN Q-Critic: 2x GCNConv(128->128) + concat(action 16) -> fc1(144->128) -> fc2(128->1)
// N = 100000 nodes, E = 1600000 edges. All fp32.
// edge_index is read as INT32 (harness materializes integer inputs as int32;
// reading it as int64 was the R1/R2 address-space trap).
// ---------------------------------------------------------------------------

#define MAX_N 100000
#define DIM   128

__device__ float g_bufA[MAX_N * DIM];
__device__ float g_bufB[MAX_N * DIM];
__device__ float g_dinv[MAX_N];

// Buffer selector: 0 = external pointer, 1 = g_bufA, 2 = g_bufB
__device__ __forceinline__ float* resolve(const float* p, int sel) {
    if (sel == 1) return g_bufA;
    if (sel == 2) return g_bufB;
    return (float*)p;
}

__device__ __forceinline__ int clampi(int v, int n) {
    return min(max(v, 0), n - 1);
}

// ---------------------------------------------------------------------------
// Degree kernels (operate on g_dinv directly)
// ---------------------------------------------------------------------------
__global__ __launch_bounds__(256) void k_init_deg(int n) {
    int i = blockIdx.x * blockDim.x + threadIdx.x;
    if (i < n) g_dinv[i] = 1.0f;  // self-loop
}

__global__ __launch_bounds__(256) void k_accum_deg(const int* __restrict__ ei,
                                                   int n_edges, int n) {
    int e = blockIdx.x * blockDim.x + threadIdx.x;
    if (e < n_edges) {
        int d = clampi(ei[n_edges + e], n);  // dst row of [2, E] int32
        atomicAdd(&g_dinv[d], 1.0f);
    }
}

__global__ __launch_bounds__(256) void k_rsqrt(int n) {
    int i = blockIdx.x * blockDim.x + threadIdx.x;
    if (i < n) g_dinv[i] = rsqrtf(g_dinv[i]);  // deg >= 1 always (self-loop)
}

// ---------------------------------------------------------------------------
// SGEMM: C[M,128] = A[M,K] @ W[K,128] (+bias)(+relu)
// A2 (optional) supplies columns 128..K-1 (the action concat, stride 16).
// BM=128, BN=128, BK=16, 256 threads, 8x8 register tile per thread.
// ---------------------------------------------------------------------------
__global__ __launch_bounds__(256) void k_sgemm(const float* __restrict__ Ap, int a_sel,
                                               const float* __restrict__ A2,
                                               const float* __restrict__ W,
                                               const float* __restrict__ bias,
                                               float* __restrict__ Cp, int c_sel,
                                               int M, int K, int do_relu) {
    const float* A = resolve(Ap, a_sel);
    float*       C = resolve(Cp, c_sel);

    __shared__ float As[16][DIM + 4];
    __shared__ float Bs[16][DIM];

    int tid = threadIdx.x;
    int m0  = blockIdx.x * 128;

    int tm = (tid >> 4) * 8;   // 0..120
    int tn = (tid & 15) * 8;   // 0..120

    float acc[8][8];
#pragma unroll
    for (int i = 0; i < 8; i++)
#pragma unroll
        for (int j = 0; j < 8; j++) acc[i][j] = 0.0f;

    int ar = tid >> 1;           // A row within tile 0..127
    int ak = (tid & 1) * 8;      // A col offset 0 or 8
    int gm = m0 + ar;

    int bk = tid >> 5;           // 0..7 (two passes: +0, +8)
    int bn = (tid & 31) * 4;     // 0..124

    int n_tiles = K / 16;
    for (int t = 0; t < n_tiles; t++) {
        int k0 = t * 16;

        float av[8];
        if (gm < M) {
            if (k0 < DIM) {
                const float4* p = reinterpret_cast<const float4*>(A + (size_t)gm * DIM + k0 + ak);
                float4 v0 = p[0], v1 = p[1];
                av[0] = v0.x; av[1] = v0.y; av[2] = v0.z; av[3] = v0.w;
                av[4] = v1.x; av[5] = v1.y; av[6] = v1.z; av[7] = v1.w;
            } else {
                const float4* p = reinterpret_cast<const float4*>(A2 + (size_t)gm * 16 + (k0 - DIM) + ak);
                float4 v0 = p[0], v1 = p[1];
                av[0] = v0.x; av[1] = v0.y; av[2] = v0.z; av[3] = v0.w;
                av[4] = v1.x; av[5] = v1.y; av[6] = v1.z; av[7] = v1.w;
            }
        } else {
#pragma unroll
            for (int i = 0; i < 8; i++) av[i] = 0.0f;
        }
#pragma unroll
        for (int i = 0; i < 8; i++) As[ak + i][ar] = av[i];

        {
            const float4* p0 = reinterpret_cast<const float4*>(W + (size_t)(k0 + bk) * DIM + bn);
            const float4* p1 = reinterpret_cast<const float4*>(W + (size_t)(k0 + bk + 8) * DIM + bn);
            *reinterpret_cast<float4*>(&Bs[bk][bn])     = *p0;
            *reinterpret_cast<float4*>(&Bs[bk + 8][bn]) = *p1;
        }
        __syncthreads();

#pragma unroll
        for (int k = 0; k < 16; k++) {
            float a[8], b[8];
            float4 a0 = *reinterpret_cast<const float4*>(&As[k][tm]);
            float4 a1 = *reinterpret_cast<const float4*>(&As[k][tm + 4]);
            float4 b0 = *reinterpret_cast<const float4*>(&Bs[k][tn]);
            float4 b1 = *reinterpret_cast<const float4*>(&Bs[k][tn + 4]);
            a[0]=a0.x; a[1]=a0.y; a[2]=a0.z; a[3]=a0.w; a[4]=a1.x; a[5]=a1.y; a[6]=a1.z; a[7]=a1.w;
            b[0]=b0.x; b[1]=b0.y; b[2]=b0.z; b[3]=b0.w; b[4]=b1.x; b[5]=b1.y; b[6]=b1.z; b[7]=b1.w;
#pragma unroll
            for (int i = 0; i < 8; i++)
#pragma unroll
                for (int j = 0; j < 8; j++) acc[i][j] = fmaf(a[i], b[j], acc[i][j]);
        }
        __syncthreads();
    }

    float bv[8];
    if (bias) {
#pragma unroll
        for (int j = 0; j < 8; j++) bv[j] = bias[tn + j];
    } else {
#pragma unroll
        for (int j = 0; j < 8; j++) bv[j] = 0.0f;
    }
#pragma unroll
    for (int i = 0; i < 8; i++) {
        int row = m0 + tm + i;
        if (row < M) {
            float4 o0, o1;
            float v[8];
#pragma unroll
            for (int j = 0; j < 8; j++) {
                float c = acc[i][j] + bv[j];
                if (do_relu) c = fmaxf(c, 0.0f);
                v[j] = c;
            }
            o0.x=v[0]; o0.y=v[1]; o0.z=v[2]; o0.w=v[3];
            o1.x=v[4]; o1.y=v[5]; o1.z=v[6]; o1.w=v[7];
            float4* cp = reinterpret_cast<float4*>(C + (size_t)row * DIM + tn);
            cp[0] = o0; cp[1] = o1;
        }
    }
}

// ---------------------------------------------------------------------------
// Self-loop init: out[v] = xw[v] * dinv[v]^2
// ---------------------------------------------------------------------------
__global__ __launch_bounds__(256) void k_selfloop(int xw_sel, int out_sel, int n) {
    const float* xw = resolve(nullptr, xw_sel);
    float*       out = resolve(nullptr, out_sel);
    int i4 = blockIdx.x * blockDim.x + threadIdx.x;
    int total = n * (DIM / 4);
    if (i4 < total) {
        int row = i4 >> 5;  // 32 float4 per row
        float s = g_dinv[row];
        float s2 = s * s;
        float4 v = reinterpret_cast<const float4*>(xw)[i4];
        v.x *= s2; v.y *= s2; v.z *= s2; v.w *= s2;
        reinterpret_cast<float4*>(out)[i4] = v;
    }
}

// ---------------------------------------------------------------------------
// Edge scatter: one warp per edge, 4 scalar atomicAdd per lane (-> REDG)
// ---------------------------------------------------------------------------
__global__ __launch_bounds__(256) void k_scatter(const int* __restrict__ ei,
                                                 int xw_sel, int out_sel,
                                                 int n_edges, int n) {
    const float* xw  = resolve(nullptr, xw_sel);
    float*       out = resolve(nullptr, out_sel);
    int t = blockIdx.x * blockDim.x + threadIdx.x;
    int e = t >> 5;
    int lane = t & 31;
    if (e >= n_edges) return;

    int s = clampi(ei[e], n);
    int d = clampi(ei[n_edges + e], n);
    float norm = g_dinv[s] * g_dinv[d];

    float4 v = reinterpret_cast<const float4*>(xw + (size_t)s * DIM)[lane];

    float* dp = out + (size_t)d * DIM + lane * 4;
    atomicAdd(dp + 0, v.x * norm);
    atomicAdd(dp + 1, v.y * norm);
    atomicAdd(dp + 2, v.z * norm);
    atomicAdd(dp + 3, v.w * norm);
}

// ---------------------------------------------------------------------------
// Bias + ReLU (in place)
// ---------------------------------------------------------------------------
__global__ __launch_bounds__(256) void k_bias_relu(int buf_sel,
                                                   const float* __restrict__ bias, int n) {
    float* buf = resolve(nullptr, buf_sel);
    int i4 = blockIdx.x * blockDim.x + threadIdx.x;
    int total = n * (DIM / 4);
    if (i4 < total) {
        int c4 = i4 & 31;
        float4 b = reinterpret_cast<const float4*>(bias)[c4];
        float4 v = reinterpret_cast<float4*>(buf)[i4];
        v.x = fmaxf(v.x + b.x, 0.0f);
        v.y = fmaxf(v.y + b.y, 0.0f);
        v.z = fmaxf(v.z + b.z, 0.0f);
        v.w = fmaxf(v.w + b.w, 0.0f);
        reinterpret_cast<float4*>(buf)[i4] = v;
    }
}

// ---------------------------------------------------------------------------
// fc2: q[i] = dot(h[i,:], w) + b   (one warp per node)
// ---------------------------------------------------------------------------
__global__ __launch_bounds__(256) void k_fc2(int h_sel,
                                             const float* __restrict__ w,
                                             const float* __restrict__ b,
                                             float* __restrict__ out, int n) {
    const float* h = resolve(nullptr, h_sel);
    int t = blockIdx.x * blockDim.x + threadIdx.x;
    int row = t >> 5;
    int lane = t & 31;
    if (row >= n) return;
    float4 hv = reinterpret_cast<const float4*>(h + (size_t)row * DIM)[lane];
    float4 wv = reinterpret_cast<const float4*>(w)[lane];
    float sum = hv.x * wv.x + hv.y * wv.y + hv.z * wv.z + hv.w * wv.w;
#pragma unroll
    for (int off = 16; off > 0; off >>= 1)
        sum += __shfl_xor_sync(0xFFFFFFFFu, sum, off);
    if (lane == 0) out[row] = sum + b[0];
}

// ---------------------------------------------------------------------------
// Host launcher
// ---------------------------------------------------------------------------
extern "C" void kernel_launch(void* const* d_in, const int* in_sizes, int n_in,
                              void* d_out, int out_size) {
    const float* x      = (const float*)d_in[0];
    const int*   ei     = (const int*)d_in[1];     // int32 [2, E]
    const float* action = (const float*)d_in[2];
    const float* w1     = (const float*)d_in[3];
    const float* b1     = (const float*)d_in[4];
    const float* w2     = (const float*)d_in[5];
    const float* b2     = (const float*)d_in[6];
    const float* fw1    = (const float*)d_in[7];
    const float* fb1    = (const float*)d_in[8];
    const float* fw2    = (const float*)d_in[9];
    const float* fb2    = (const float*)d_in[10];

    int N = in_sizes[0] / DIM;
    int E = in_sizes[1] / 2;

    int nb256       = (N + 255) / 256;
    int eb256       = (E + 255) / 256;
    int ew_blocks   = (int)(((long long)E * 32 + 255) / 256);  // one warp per edge
    int v4_blocks   = (N * (DIM / 4) + 255) / 256;
    int gemm_blocks = (N + 127) / 128;
    int warp_blocks = (int)(((long long)N * 32 + 255) / 256);

    // degrees -> dinv
    k_init_deg <<<nb256, 256>>>(N);
    k_accum_deg<<<eb256, 256>>>(ei, E, N);
    k_rsqrt    <<<nb256, 256>>>(N);

    // ---- GCN layer 1 ----  (A: x -> bufA, aggregate -> bufB)
    k_sgemm    <<<gemm_blocks, 256>>>(x, 0, nullptr, w1, nullptr, nullptr, 1, N, DIM, 0);
    k_selfloop <<<v4_blocks, 256>>>(1, 2, N);
    k_scatter  <<<ew_blocks, 256>>>(ei, 1, 2, E, N);
    k_bias_relu<<<v4_blocks, 256>>>(2, b1, N);

    // ---- GCN layer 2 ----  (A: bufB -> bufA, aggregate -> bufB)
    k_sgemm    <<<gemm_blocks, 256>>>(nullptr, 2, nullptr, w2, nullptr, nullptr, 1, N, DIM, 0);
    k_selfloop <<<v4_blocks, 256>>>(1, 2, N);
    k_scatter  <<<ew_blocks, 256>>>(ei, 1, 2, E, N);
    k_bias_relu<<<v4_blocks, 256>>>(2, b2, N);

    // ---- MLP head ----  (bufB + action -> bufA -> q)
    k_sgemm<<<gemm_blocks, 256>>>(nullptr, 2, action, fw1, fb1, nullptr, 1, N, DIM + 16, 1);
    k_fc2  <<<warp_blocks, 256>>>(1, fw2, fb2, (float*)d_out, N);
}

// round 5
// speedup vs baseline: 1.6206x; 1.6206x over previous
#include <cuda_runtime.h>
#include <cstdint>

// ---------------------------------------------------------------------------
// GCN Q-Critic: 2x GCNConv(128->128) + concat(action 16) -> fc1(144->128) -> fc2(128->1)
// N = 100000 nodes, E = 1600000 edges. All fp32. edge_index = int32 [2, E].
//
// R4: vector reds (red.global.add.v4.f32), dinv folded into GEMM epilogue
// (y = xw*dinv), prev-layer bias+relu folded into GEMM A-load, fc2 fused
// into the fc1 GEMM epilogue.
// ---------------------------------------------------------------------------

#define MAX_N 100000
#define DIM   128

__device__ float g_bufA[MAX_N * DIM];   // y (scaled GEMM output)
__device__ float g_bufB[MAX_N * DIM];   // aggregated output
__device__ float g_dinv[MAX_N];

// Buffer selector: 0 = external pointer, 1 = g_bufA, 2 = g_bufB
__device__ __forceinline__ float* resolve(const float* p, int sel) {
    if (sel == 1) return g_bufA;
    if (sel == 2) return g_bufB;
    return (float*)p;
}

__device__ __forceinline__ int clampi(int v, int n) {
    return min(max(v, 0), n - 1);
}

// ---------------------------------------------------------------------------
// Degree kernels
// ---------------------------------------------------------------------------
__global__ __launch_bounds__(256) void k_init_deg(int n) {
    int i = blockIdx.x * blockDim.x + threadIdx.x;
    if (i < n) g_dinv[i] = 1.0f;  // self-loop
}

__global__ __launch_bounds__(256) void k_accum_deg(const int* __restrict__ ei,
                                                   int n_edges, int n) {
    int e = blockIdx.x * blockDim.x + threadIdx.x;
    if (e < n_edges) {
        int d = clampi(ei[n_edges + e], n);
        atomicAdd(&g_dinv[d], 1.0f);
    }
}

__global__ __launch_bounds__(256) void k_rsqrt(int n) {
    int i = blockIdx.x * blockDim.x + threadIdx.x;
    if (i < n) g_dinv[i] = rsqrtf(g_dinv[i]);
}

// ---------------------------------------------------------------------------
// SGEMM: C[M,128] = f(A)[M,K] @ W[K,128]
//   f(A): if in_bias != null, A-main-region values become relu(a + in_bias[col])
//         (A2/action region is loaded raw)
//   epilogue: if q_out == null: C = acc * (dinv[row] if scale_dinv)
//             else: fused fc1+fc2: h = relu(acc + fc1_b), q = h . fc2_w + fc2_b
// BM=128, BN=128, BK=16, 256 threads, 8x8 register tile.
// ---------------------------------------------------------------------------
__global__ __launch_bounds__(256) void k_sgemm(const float* __restrict__ Ap, int a_sel,
                                               const float* __restrict__ A2,
                                               const float* __restrict__ W,
                                               const float* __restrict__ in_bias,
                                               float* __restrict__ Cp, int c_sel,
                                               int M, int K, int scale_dinv,
                                               const float* __restrict__ fc1_b,
                                               const float* __restrict__ fc2_w,
                                               const float* __restrict__ fc2_b,
                                               float* __restrict__ q_out) {
    const float* A = resolve(Ap, a_sel);
    float*       C = resolve(Cp, c_sel);

    __shared__ float As[16][DIM + 4];
    __shared__ float Bs[16][DIM];
    __shared__ float Red[128][17];   // fc2 row-reduce scratch

    int tid = threadIdx.x;
    int m0  = blockIdx.x * 128;

    int tm = (tid >> 4) * 8;   // 0..120
    int tn = (tid & 15) * 8;   // 0..120

    float acc[8][8];
#pragma unroll
    for (int i = 0; i < 8; i++)
#pragma unroll
        for (int j = 0; j < 8; j++) acc[i][j] = 0.0f;

    int ar = tid >> 1;           // A row within tile 0..127
    int ak = (tid & 1) * 8;      // A col offset 0 or 8
    int gm = m0 + ar;

    int bk = tid >> 5;           // 0..7 (two passes: +0, +8)
    int bn = (tid & 31) * 4;     // 0..124

    int n_tiles = K / 16;
    for (int t = 0; t < n_tiles; t++) {
        int k0 = t * 16;

        float av[8];
        if (gm < M) {
            if (k0 < DIM) {
                const float4* p = reinterpret_cast<const float4*>(A + (size_t)gm * DIM + k0 + ak);
                float4 v0 = p[0], v1 = p[1];
                av[0] = v0.x; av[1] = v0.y; av[2] = v0.z; av[3] = v0.w;
                av[4] = v1.x; av[5] = v1.y; av[6] = v1.z; av[7] = v1.w;
                if (in_bias) {
                    const float4* bp = reinterpret_cast<const float4*>(in_bias + k0 + ak);
                    float4 b0 = bp[0], b1 = bp[1];
                    av[0] = fmaxf(av[0] + b0.x, 0.0f);
                    av[1] = fmaxf(av[1] + b0.y, 0.0f);
                    av[2] = fmaxf(av[2] + b0.z, 0.0f);
                    av[3] = fmaxf(av[3] + b0.w, 0.0f);
                    av[4] = fmaxf(av[4] + b1.x, 0.0f);
                    av[5] = fmaxf(av[5] + b1.y, 0.0f);
                    av[6] = fmaxf(av[6] + b1.z, 0.0f);
                    av[7] = fmaxf(av[7] + b1.w, 0.0f);
                }
            } else {
                const float4* p = reinterpret_cast<const float4*>(A2 + (size_t)gm * 16 + (k0 - DIM) + ak);
                float4 v0 = p[0], v1 = p[1];
                av[0] = v0.x; av[1] = v0.y; av[2] = v0.z; av[3] = v0.w;
                av[4] = v1.x; av[5] = v1.y; av[6] = v1.z; av[7] = v1.w;
            }
        } else {
#pragma unroll
            for (int i = 0; i < 8; i++) av[i] = 0.0f;
        }
#pragma unroll
        for (int i = 0; i < 8; i++) As[ak + i][ar] = av[i];

        {
            const float4* p0 = reinterpret_cast<const float4*>(W + (size_t)(k0 + bk) * DIM + bn);
            const float4* p1 = reinterpret_cast<const float4*>(W + (size_t)(k0 + bk + 8) * DIM + bn);
            *reinterpret_cast<float4*>(&Bs[bk][bn])     = *p0;
            *reinterpret_cast<float4*>(&Bs[bk + 8][bn]) = *p1;
        }
        __syncthreads();

#pragma unroll
        for (int k = 0; k < 16; k++) {
            float a[8], b[8];
            float4 a0 = *reinterpret_cast<const float4*>(&As[k][tm]);
            float4 a1 = *reinterpret_cast<const float4*>(&As[k][tm + 4]);
            float4 b0 = *reinterpret_cast<const float4*>(&Bs[k][tn]);
            float4 b1 = *reinterpret_cast<const float4*>(&Bs[k][tn + 4]);
            a[0]=a0.x; a[1]=a0.y; a[2]=a0.z; a[3]=a0.w; a[4]=a1.x; a[5]=a1.y; a[6]=a1.z; a[7]=a1.w;
            b[0]=b0.x; b[1]=b0.y; b[2]=b0.z; b[3]=b0.w; b[4]=b1.x; b[5]=b1.y; b[6]=b1.z; b[7]=b1.w;
#pragma unroll
            for (int i = 0; i < 8; i++)
#pragma unroll
                for (int j = 0; j < 8; j++) acc[i][j] = fmaf(a[i], b[j], acc[i][j]);
        }
        __syncthreads();
    }

    if (q_out == nullptr) {
        // ---- plain epilogue: C = acc * (dinv[row]?) ----
#pragma unroll
        for (int i = 0; i < 8; i++) {
            int row = m0 + tm + i;
            if (row < M) {
                float s = scale_dinv ? g_dinv[row] : 1.0f;
                float4 o0, o1;
                o0.x = acc[i][0] * s; o0.y = acc[i][1] * s;
                o0.z = acc[i][2] * s; o0.w = acc[i][3] * s;
                o1.x = acc[i][4] * s; o1.y = acc[i][5] * s;
                o1.z = acc[i][6] * s; o1.w = acc[i][7] * s;
                float4* cp = reinterpret_cast<float4*>(C + (size_t)row * DIM + tn);
                cp[0] = o0; cp[1] = o1;
            }
        }
    } else {
        // ---- fused fc1 (bias+relu) + fc2 (dot) epilogue ----
        float fb[8], fw[8];
#pragma unroll
        for (int j = 0; j < 8; j++) { fb[j] = fc1_b[tn + j]; fw[j] = fc2_w[tn + j]; }
#pragma unroll
        for (int i = 0; i < 8; i++) {
            float p = 0.0f;
#pragma unroll
            for (int j = 0; j < 8; j++) {
                float h = fmaxf(acc[i][j] + fb[j], 0.0f);
                p = fmaf(h, fw[j], p);
            }
            Red[tm + i][tid & 15] = p;
        }
        __syncthreads();
        if (tid < 128) {
            int row = m0 + tid;
            if (row < M) {
                float s = fc2_b[0];
#pragma unroll
                for (int j = 0; j < 16; j++) s += Red[tid][j];
                q_out[row] = s;
            }
        }
    }
}

// ---------------------------------------------------------------------------
// Self-loop init: out[v] = y[v] * dinv[v]   (y already = xw*dinv)
// ---------------------------------------------------------------------------
__global__ __launch_bounds__(256) void k_selfloop(int y_sel, int out_sel, int n) {
    const float* y   = resolve(nullptr, y_sel);
    float*       out = resolve(nullptr, out_sel);
    int i4 = blockIdx.x * blockDim.x + threadIdx.x;
    int total = n * (DIM / 4);
    if (i4 < total) {
        int row = i4 >> 5;
        float s = g_dinv[row];
        float4 v = reinterpret_cast<const float4*>(y)[i4];
        v.x *= s; v.y *= s; v.z *= s; v.w *= s;
        reinterpret_cast<float4*>(out)[i4] = v;
    }
}

// ---------------------------------------------------------------------------
// Edge scatter: one warp per edge; msg = y[src]*dinv[dst]; one v4 RED per lane
// ---------------------------------------------------------------------------
__global__ __launch_bounds__(256) void k_scatter(const int* __restrict__ ei,
                                                 int y_sel, int out_sel,
                                                 int n_edges, int n) {
    const float* y   = resolve(nullptr, y_sel);
    float*       out = resolve(nullptr, out_sel);
    int t = blockIdx.x * blockDim.x + threadIdx.x;
    int e = t >> 5;
    int lane = t & 31;
    if (e >= n_edges) return;

    int s = clampi(ei[e], n);
    int d = clampi(ei[n_edges + e], n);
    float dd = g_dinv[d];

    float4 v = reinterpret_cast<const float4*>(y + (size_t)s * DIM)[lane];
    v.x *= dd; v.y *= dd; v.z *= dd; v.w *= dd;

    float* dp = out + (size_t)d * DIM + lane * 4;
    asm volatile("red.global.add.v4.f32 [%0], {%1, %2, %3, %4};"
                 :: "l"(dp), "f"(v.x), "f"(v.y), "f"(v.z), "f"(v.w)
                 : "memory");
}

// ---------------------------------------------------------------------------
// Host launcher
// ---------------------------------------------------------------------------
extern "C" void kernel_launch(void* const* d_in, const int* in_sizes, int n_in,
                              void* d_out, int out_size) {
    const float* x      = (const float*)d_in[0];
    const int*   ei     = (const int*)d_in[1];     // int32 [2, E]
    const float* action = (const float*)d_in[2];
    const float* w1     = (const float*)d_in[3];
    const float* b1     = (const float*)d_in[4];
    const float* w2     = (const float*)d_in[5];
    const float* b2     = (const float*)d_in[6];
    const float* fw1    = (const float*)d_in[7];
    const float* fb1    = (const float*)d_in[8];
    const float* fw2    = (const float*)d_in[9];
    const float* fb2    = (const float*)d_in[10];

    int N = in_sizes[0] / DIM;
    int E = in_sizes[1] / 2;

    int nb256       = (N + 255) / 256;
    int eb256       = (E + 255) / 256;
    int ew_blocks   = (int)(((long long)E * 32 + 255) / 256);
    int v4_blocks   = (N * (DIM / 4) + 255) / 256;
    int gemm_blocks = (N + 127) / 128;

    // degrees -> dinv
    k_init_deg <<<nb256, 256>>>(N);
    k_accum_deg<<<eb256, 256>>>(ei, E, N);
    k_rsqrt    <<<nb256, 256>>>(N);

    // ---- GCN layer 1 ----  y1 = (x@W1)*dinv -> bufA; aggregate -> bufB
    k_sgemm   <<<gemm_blocks, 256>>>(x, 0, nullptr, w1, nullptr,
                                     nullptr, 1, N, DIM, 1,
                                     nullptr, nullptr, nullptr, nullptr);
    k_selfloop<<<v4_blocks, 256>>>(1, 2, N);
    k_scatter <<<ew_blocks, 256>>>(ei, 1, 2, E, N);

    // ---- GCN layer 2 ----  y2 = (relu(agg1+b1)@W2)*dinv -> bufA; aggregate -> bufB
    k_sgemm   <<<gemm_blocks, 256>>>(nullptr, 2, nullptr, w2, b1,
                                     nullptr, 1, N, DIM, 1,
                                     nullptr, nullptr, nullptr, nullptr);
    k_selfloop<<<v4_blocks, 256>>>(1, 2, N);
    k_scatter <<<ew_blocks, 256>>>(ei, 1, 2, E, N);

    // ---- MLP head ----  q = relu([relu(agg2+b2), action]@fw1 + fb1) . fw2 + fb2
    k_sgemm<<<gemm_blocks, 256>>>(nullptr, 2, action, fw1, b2,
                                  nullptr, 0, N, DIM + 16, 0,
                                  fb1, fw2, fb2, (float*)d_out);
}

// round 7
// speedup vs baseline: 2.7296x; 1.6843x over previous
#include <cuda_runtime.h>
#include <cstdint>

// ---------------------------------------------------------------------------
// GCN Q-Critic: 2x GCNConv(128->128) + concat(action 16) -> fc1(144->128) -> fc2(128->1)
// N = 100000 nodes, E = 1600000 edges. fp32. edge_index = int32 [2, E].
//
// R5: atomic edge-scatter replaced by in-kernel CSR build (count + scan + fill)
// and an atomic-free warp-per-node gather-aggregate with fused self-loop+dinv.
// ---------------------------------------------------------------------------

#define MAX_N 100000
#define MAX_E 1700000
#define DIM   128

__device__ float g_bufA[MAX_N * DIM];   // y = (A@W)*dinv
__device__ float g_bufB[MAX_N * DIM];   // aggregated output
__device__ float g_dinv[MAX_N];
__device__ int   g_deg[MAX_N];
__device__ int   g_row[MAX_N + 1];
__device__ int   g_cursor[MAX_N];
__device__ int   g_csr_src[MAX_E];
__device__ int   g_bsum[1024];

__device__ __forceinline__ float* resolve(int sel) {
    return (sel == 1) ? g_bufA : g_bufB;
}
__device__ __forceinline__ int clampi(int v, int n) {
    return min(max(v, 0), n - 1);
}

// ---------------------------------------------------------------------------
// CSR build
// ---------------------------------------------------------------------------
__global__ __launch_bounds__(256) void k_zero_deg(int n) {
    int i = blockIdx.x * blockDim.x + threadIdx.x;
    if (i < n) g_deg[i] = 0;
}

__global__ __launch_bounds__(256) void k_count_deg(const int* __restrict__ ei,
                                                   int n_edges, int n) {
    int e = blockIdx.x * blockDim.x + threadIdx.x;
    if (e < n_edges) atomicAdd(&g_deg[clampi(ei[n_edges + e], n)], 1);
}

__global__ __launch_bounds__(256) void k_dinv(int n) {
    int i = blockIdx.x * blockDim.x + threadIdx.x;
    if (i < n) g_dinv[i] = rsqrtf((float)(g_deg[i] + 1));  // +1 self-loop
}

// scan stage 1: per-block inclusive scan of 256 degrees -> exclusive to g_row,
// block total to g_bsum
__global__ __launch_bounds__(256) void k_scan1(int n) {
    __shared__ int sm[256];
    int i = blockIdx.x * 256 + threadIdx.x;
    int v = (i < n) ? g_deg[i] : 0;
    sm[threadIdx.x] = v;
    __syncthreads();
#pragma unroll
    for (int off = 1; off < 256; off <<= 1) {
        int t = (threadIdx.x >= off) ? sm[threadIdx.x - off] : 0;
        __syncthreads();
        sm[threadIdx.x] += t;
        __syncthreads();
    }
    if (i < n) g_row[i] = sm[threadIdx.x] - v;   // exclusive (partial)
    if (threadIdx.x == 255) g_bsum[blockIdx.x] = sm[255];
}

// scan stage 2: one block, exclusive scan of up to 1024 block sums
__global__ __launch_bounds__(1024) void k_scan2(int nb) {
    __shared__ int sm[1024];
    int t = threadIdx.x;
    int v = (t < nb) ? g_bsum[t] : 0;
    sm[t] = v;
    __syncthreads();
#pragma unroll
    for (int off = 1; off < 1024; off <<= 1) {
        int u = (t >= off) ? sm[t - off] : 0;
        __syncthreads();
        sm[t] += u;
        __syncthreads();
    }
    if (t < nb) g_bsum[t] = sm[t] - v;   // exclusive
}

// scan stage 3: add block offsets, init cursor, close row_ptr
__global__ __launch_bounds__(256) void k_scan3(int n, int n_edges) {
    int i = blockIdx.x * 256 + threadIdx.x;
    if (i < n) {
        int r = g_row[i] + g_bsum[blockIdx.x];
        g_row[i] = r;
        g_cursor[i] = r;
    }
    if (i == 0) g_row[n] = n_edges;
}

__global__ __launch_bounds__(256) void k_fill(const int* __restrict__ ei,
                                              int n_edges, int n) {
    int e = blockIdx.x * blockDim.x + threadIdx.x;
    if (e < n_edges) {
        int s = clampi(ei[e], n);
        int d = clampi(ei[n_edges + e], n);
        int pos = atomicAdd(&g_cursor[d], 1);
        g_csr_src[pos] = s;
    }
}

// ---------------------------------------------------------------------------
// SGEMM: C[M,128] = f(A)[M,K] @ W[K,128]
//   f(A): if in_bias != null, main-region A becomes relu(a + in_bias[col])
//   epilogue: if q_out == null: C = acc * (dinv[row] if scale_dinv)
//             else fused fc1(bias+relu)+fc2(dot) -> q_out
// ---------------------------------------------------------------------------
__global__ __launch_bounds__(256) void k_sgemm(const float* __restrict__ Aext,
                                               int a_sel,
                                               const float* __restrict__ A2,
                                               const float* __restrict__ W,
                                               const float* __restrict__ in_bias,
                                               int c_sel,
                                               int M, int K, int scale_dinv,
                                               const float* __restrict__ fc1_b,
                                               const float* __restrict__ fc2_w,
                                               const float* __restrict__ fc2_b,
                                               float* __restrict__ q_out) {
    const float* A = (a_sel == 0) ? Aext : resolve(a_sel);
    float*       C = resolve(c_sel);

    __shared__ float As[16][DIM + 4];
    __shared__ float Bs[16][DIM];
    __shared__ float Red[128][17];

    int tid = threadIdx.x;
    int m0  = blockIdx.x * 128;
    int tm = (tid >> 4) * 8;
    int tn = (tid & 15) * 8;

    float acc[8][8];
#pragma unroll
    for (int i = 0; i < 8; i++)
#pragma unroll
        for (int j = 0; j < 8; j++) acc[i][j] = 0.0f;

    int ar = tid >> 1;
    int ak = (tid & 1) * 8;
    int gm = m0 + ar;
    int bk = tid >> 5;
    int bn = (tid & 31) * 4;

    int n_tiles = K / 16;
    for (int t = 0; t < n_tiles; t++) {
        int k0 = t * 16;
        float av[8];
        if (gm < M) {
            if (k0 < DIM) {
                const float4* p = reinterpret_cast<const float4*>(A + (size_t)gm * DIM + k0 + ak);
                float4 v0 = p[0], v1 = p[1];
                av[0]=v0.x; av[1]=v0.y; av[2]=v0.z; av[3]=v0.w;
                av[4]=v1.x; av[5]=v1.y; av[6]=v1.z; av[7]=v1.w;
                if (in_bias) {
                    const float4* bp = reinterpret_cast<const float4*>(in_bias + k0 + ak);
                    float4 b0 = bp[0], b1 = bp[1];
                    av[0]=fmaxf(av[0]+b0.x,0.f); av[1]=fmaxf(av[1]+b0.y,0.f);
                    av[2]=fmaxf(av[2]+b0.z,0.f); av[3]=fmaxf(av[3]+b0.w,0.f);
                    av[4]=fmaxf(av[4]+b1.x,0.f); av[5]=fmaxf(av[5]+b1.y,0.f);
                    av[6]=fmaxf(av[6]+b1.z,0.f); av[7]=fmaxf(av[7]+b1.w,0.f);
                }
            } else {
                const float4* p = reinterpret_cast<const float4*>(A2 + (size_t)gm * 16 + (k0 - DIM) + ak);
                float4 v0 = p[0], v1 = p[1];
                av[0]=v0.x; av[1]=v0.y; av[2]=v0.z; av[3]=v0.w;
                av[4]=v1.x; av[5]=v1.y; av[6]=v1.z; av[7]=v1.w;
            }
        } else {
#pragma unroll
            for (int i = 0; i < 8; i++) av[i] = 0.0f;
        }
#pragma unroll
        for (int i = 0; i < 8; i++) As[ak + i][ar] = av[i];

        {
            const float4* p0 = reinterpret_cast<const float4*>(W + (size_t)(k0 + bk) * DIM + bn);
            const float4* p1 = reinterpret_cast<const float4*>(W + (size_t)(k0 + bk + 8) * DIM + bn);
            *reinterpret_cast<float4*>(&Bs[bk][bn])     = *p0;
            *reinterpret_cast<float4*>(&Bs[bk + 8][bn]) = *p1;
        }
        __syncthreads();

#pragma unroll
        for (int k = 0; k < 16; k++) {
            float a[8], b[8];
            float4 a0 = *reinterpret_cast<const float4*>(&As[k][tm]);
            float4 a1 = *reinterpret_cast<const float4*>(&As[k][tm + 4]);
            float4 b0 = *reinterpret_cast<const float4*>(&Bs[k][tn]);
            float4 b1 = *reinterpret_cast<const float4*>(&Bs[k][tn + 4]);
            a[0]=a0.x; a[1]=a0.y; a[2]=a0.z; a[3]=a0.w; a[4]=a1.x; a[5]=a1.y; a[6]=a1.z; a[7]=a1.w;
            b[0]=b0.x; b[1]=b0.y; b[2]=b0.z; b[3]=b0.w; b[4]=b1.x; b[5]=b1.y; b[6]=b1.z; b[7]=b1.w;
#pragma unroll
            for (int i = 0; i < 8; i++)
#pragma unroll
                for (int j = 0; j < 8; j++) acc[i][j] = fmaf(a[i], b[j], acc[i][j]);
        }
        __syncthreads();
    }

    if (q_out == nullptr) {
#pragma unroll
        for (int i = 0; i < 8; i++) {
            int row = m0 + tm + i;
            if (row < M) {
                float s = scale_dinv ? g_dinv[row] : 1.0f;
                float4 o0, o1;
                o0.x=acc[i][0]*s; o0.y=acc[i][1]*s; o0.z=acc[i][2]*s; o0.w=acc[i][3]*s;
                o1.x=acc[i][4]*s; o1.y=acc[i][5]*s; o1.z=acc[i][6]*s; o1.w=acc[i][7]*s;
                float4* cp = reinterpret_cast<float4*>(C + (size_t)row * DIM + tn);
                cp[0]=o0; cp[1]=o1;
            }
        }
    } else {
        float fb[8], fw[8];
#pragma unroll
        for (int j = 0; j < 8; j++) { fb[j] = fc1_b[tn + j]; fw[j] = fc2_w[tn + j]; }
#pragma unroll
        for (int i = 0; i < 8; i++) {
            float p = 0.0f;
#pragma unroll
            for (int j = 0; j < 8; j++) {
                float h = fmaxf(acc[i][j] + fb[j], 0.0f);
                p = fmaf(h, fw[j], p);
            }
            Red[tm + i][tid & 15] = p;
        }
        __syncthreads();
        if (tid < 128) {
            int row = m0 + tid;
            if (row < M) {
                float s = fc2_b[0];
#pragma unroll
                for (int j = 0; j < 16; j++) s += Red[tid][j];
                q_out[row] = s;
            }
        }
    }
}

// ---------------------------------------------------------------------------
// Gather-aggregate: warp per node.
// out[v] = dinv[v] * ( y[v] + sum_{src in CSR(v)} y[src] )
// (y already carries the src-side dinv factor from the GEMM epilogue)
// ---------------------------------------------------------------------------
__global__ __launch_bounds__(256) void k_aggregate(int y_sel, int out_sel, int n) {
    const float* y   = resolve(y_sel);
    float*       out = resolve(out_sel);
    int t = blockIdx.x * blockDim.x + threadIdx.x;
    int v = t >> 5;
    int lane = t & 31;
    if (v >= n) return;

    int beg = g_row[v];
    int end = g_row[v + 1];

    float4 acc = reinterpret_cast<const float4*>(y + (size_t)v * DIM)[lane];

    for (int base = beg; base < end; base += 32) {
        int idx = base + lane;
        int sv = (idx < end) ? g_csr_src[idx] : 0;
        int cnt = min(32, end - base);
        int j = 0;
        for (; j + 4 <= cnt; j += 4) {
            int s0 = __shfl_sync(0xFFFFFFFFu, sv, j);
            int s1 = __shfl_sync(0xFFFFFFFFu, sv, j + 1);
            int s2 = __shfl_sync(0xFFFFFFFFu, sv, j + 2);
            int s3 = __shfl_sync(0xFFFFFFFFu, sv, j + 3);
            float4 t0 = reinterpret_cast<const float4*>(y + (size_t)s0 * DIM)[lane];
            float4 t1 = reinterpret_cast<const float4*>(y + (size_t)s1 * DIM)[lane];
            float4 t2 = reinterpret_cast<const float4*>(y + (size_t)s2 * DIM)[lane];
            float4 t3 = reinterpret_cast<const float4*>(y + (size_t)s3 * DIM)[lane];
            acc.x += t0.x + t1.x + t2.x + t3.x;
            acc.y += t0.y + t1.y + t2.y + t3.y;
            acc.z += t0.z + t1.z + t2.z + t3.z;
            acc.w += t0.w + t1.w + t2.w + t3.w;
        }
        for (; j < cnt; j++) {
            int s = __shfl_sync(0xFFFFFFFFu, sv, j);
            float4 tv = reinterpret_cast<const float4*>(y + (size_t)s * DIM)[lane];
            acc.x += tv.x; acc.y += tv.y; acc.z += tv.z; acc.w += tv.w;
        }
    }

    float dd = g_dinv[v];
    acc.x *= dd; acc.y *= dd; acc.z *= dd; acc.w *= dd;
    reinterpret_cast<float4*>(out + (size_t)v * DIM)[lane] = acc;
}

// ---------------------------------------------------------------------------
// Host launcher
// ---------------------------------------------------------------------------
extern "C" void kernel_launch(void* const* d_in, const int* in_sizes, int n_in,
                              void* d_out, int out_size) {
    const float* x      = (const float*)d_in[0];
    const int*   ei     = (const int*)d_in[1];
    const float* action = (const float*)d_in[2];
    const float* w1     = (const float*)d_in[3];
    const float* b1     = (const float*)d_in[4];
    const float* w2     = (const float*)d_in[5];
    const float* b2     = (const float*)d_in[6];
    const float* fw1    = (const float*)d_in[7];
    const float* fb1    = (const float*)d_in[8];
    const float* fw2    = (const float*)d_in[9];
    const float* fb2    = (const float*)d_in[10];

    int N = in_sizes[0] / DIM;
    int E = in_sizes[1] / 2;

    int nb256       = (N + 255) / 256;
    int eb256       = (E + 255) / 256;
    int gemm_blocks = (N + 127) / 128;
    int agg_blocks  = (int)(((long long)N * 32 + 255) / 256);

    // ---- CSR build + dinv ----
    k_zero_deg <<<nb256, 256>>>(N);
    k_count_deg<<<eb256, 256>>>(ei, E, N);
    k_dinv     <<<nb256, 256>>>(N);
    k_scan1    <<<nb256, 256>>>(N);
    k_scan2    <<<1, 1024>>>(nb256);
    k_scan3    <<<nb256, 256>>>(N, E);
    k_fill     <<<eb256, 256>>>(ei, E, N);

    // ---- GCN layer 1 ----  y1 = (x@W1)*dinv -> bufA; aggregate -> bufB
    k_sgemm    <<<gemm_blocks, 256>>>(x, 0, nullptr, w1, nullptr,
                                      1, N, DIM, 1,
                                      nullptr, nullptr, nullptr, nullptr);
    k_aggregate<<<agg_blocks, 256>>>(1, 2, N);

    // ---- GCN layer 2 ----  y2 = (relu(agg1+b1)@W2)*dinv -> bufA; aggregate -> bufB
    k_sgemm    <<<gemm_blocks, 256>>>(nullptr, 2, nullptr, w2, b1,
                                      1, N, DIM, 1,
                                      nullptr, nullptr, nullptr, nullptr);
    k_aggregate<<<agg_blocks, 256>>>(1, 2, N);

    // ---- MLP head ----  q = relu([relu(agg2+b2), action]@fw1 + fb1) . fw2 + fb2
    k_sgemm<<<gemm_blocks, 256>>>(nullptr, 2, action, fw1, b2,
                                  1, N, DIM + 16, 0,
                                  fb1, fw2, fb2, (float*)d_out);
}